// round 16
// baseline (speedup 1.0000x reference)
#include <cuda_runtime.h>
#include <math.h>

// Problem constants
#define BATCH   4
#define CHANS   64
#define NBC     256                 // BATCH * CHANS
#define SPATIAL 524288              // 32*128*128 elements per (b,c)
#define SPAT4   131072              // SPATIAL / 4 (float4)
#define PARTS   8                   // reduction blocks per (b,c)
#define REDR    4                   // C // R = 64/16
#define NRED    (NBC * PARTS)       // 2048 reduce blocks
#define KEEP_BC 48                  // bc < KEEP_BC (96 MiB) kept L2-resident

// Deterministic scratch (no device allocation allowed).
__device__ float g_part_s [NRED];   // [part][bc] layout (coalesced epilogue)
__device__ float g_part_ss[NRED];
__device__ float g_gate   [NBC];
__device__ unsigned int g_done;     // zero-init; reset by the last block each call

// ---------------------------------------------------------------------------
// Kernel 1: per-(b,c) partial sum / sum-of-squares, SE MLP fused into the
// last-finishing block. grid = (PARTS, NBC) = 2048 blocks.
// Cache steering: bc < KEEP_BC is read with DEFAULT policy (stays in L2,
// 96 MiB < 126 MiB capacity); everything else streams via __ldcs
// (evict-first) so it cannot displace the kept set. The scale kernel
// consumes bc 0..KEEP_BC-1 FIRST (bid dispatch order) -> L2 hits.
// PDL: non-last blocks trigger after publishing partials; the LAST block
// triggers only AFTER g_gate is published.
// ---------------------------------------------------------------------------
__global__ __launch_bounds__(256) void cca_reduce_se_kernel(
    const float4* __restrict__ x,
    const float*  __restrict__ w1, const float* __restrict__ b1,
    const float*  __restrict__ w2, const float* __restrict__ b2)
{
    const int part = blockIdx.x;      // 0..PARTS-1
    const int bc   = blockIdx.y;      // 0..NBC-1
    const int tid  = threadIdx.x;

    const float4* p = x + (size_t)bc * SPAT4 + (size_t)part * (SPAT4 / PARTS);

    float s = 0.f, ss = 0.f;
    if (bc < KEEP_BC) {
        #pragma unroll 16
        for (int k = 0; k < 64; ++k) {
            float4 v = p[tid + k * 256];               // default: keep in L2
            s  += v.x + v.y + v.z + v.w;
            ss += v.x * v.x + v.y * v.y + v.z * v.z + v.w * v.w;
        }
    } else {
        #pragma unroll 16
        for (int k = 0; k < 64; ++k) {
            float4 v = __ldcs(p + tid + k * 256);      // stream: evict-first
            s  += v.x + v.y + v.z + v.w;
            ss += v.x * v.x + v.y * v.y + v.z * v.z + v.w * v.w;
        }
    }

    // warp reduce
    #pragma unroll
    for (int o = 16; o > 0; o >>= 1) {
        s  += __shfl_xor_sync(0xffffffffu, s,  o);
        ss += __shfl_xor_sync(0xffffffffu, ss, o);
    }

    __shared__ float sh_s[8], sh_ss[8];
    __shared__ bool  sh_last;
    const int w = tid >> 5;
    if ((tid & 31) == 0) { sh_s[w] = s; sh_ss[w] = ss; }
    __syncthreads();

    if (tid == 0) {
        float ts = 0.f, tss = 0.f;
        #pragma unroll
        for (int i = 0; i < 8; ++i) { ts += sh_s[i]; tss += sh_ss[i]; }
        g_part_s [part * NBC + bc] = ts;               // [part][bc] layout
        g_part_ss[part * NBC + bc] = tss;
        __threadfence();                               // publish partials
        unsigned int prev = atomicAdd(&g_done, 1u);
        sh_last = (prev == NRED - 1u);
    }
    __syncthreads();
    if (!sh_last) {
        cudaTriggerProgrammaticLaunchCompletion();     // partials published
        return;
    }

    // ---- Last block: finish reduction + SE MLP (thread t = bc index) ----
    __threadfence();                                   // acquire partials
    const int t = tid;

    float fs = 0.f, fss = 0.f;
    #pragma unroll
    for (int i = 0; i < PARTS; ++i) {                  // coalesced column reads
        fs  += g_part_s [i * NBC + t];
        fss += g_part_ss[i * NBC + t];
    }
    const float invN = 1.0f / (float)SPATIAL;
    const float mean = fs * invN;
    const float var  = fmaxf(fss * invN - mean * mean, 0.f);
    const float stdv = sqrtf(var);

    __shared__ float y[NBC];
    y[t] = stdv + mean;
    __syncthreads();

    __shared__ float h[BATCH * REDR];
    if (t < BATCH * REDR) {
        const int b = t / REDR;
        const int r = t % REDR;
        float acc = b1[r];
        #pragma unroll
        for (int c = 0; c < CHANS; ++c)
            acc += w1[r * CHANS + c] * y[b * CHANS + c];
        h[t] = fmaxf(acc, 0.f);
    }
    __syncthreads();

    const int b = t / CHANS;
    const int c = t % CHANS;
    float acc = b2[c];
    #pragma unroll
    for (int r = 0; r < REDR; ++r)
        acc += w2[c * REDR + r] * h[b * REDR + r];
    g_gate[t] = 1.0f / (1.0f + expf(-acc));

    if (t == 0) g_done = 0;                            // reset for next replay
    __threadfence();                                   // publish gate + reset
    __syncthreads();                                   // all gate writes done
    cudaTriggerProgrammaticLaunchCompletion();         // NOW release secondary
}

// ---------------------------------------------------------------------------
// Kernel 2: out = x * g[bc]. PDL secondary, sync at top. Peak granularity:
// grid (256, NBC) = 65536 blocks, 2 float4/thread. Early blocks (bc <
// KEEP_BC) read the L2-kept set with default policy; all other reads and
// ALL writes are streaming (__ldcs/__stcs) so they evict each other first
// and never displace the kept lines before they're consumed.
// ---------------------------------------------------------------------------
__global__ __launch_bounds__(256) void cca_scale_kernel(const float4* __restrict__ x,
                                                        float4* __restrict__ out) {
    cudaGridDependencySynchronize();                   // gate provably visible

    const int bc = blockIdx.y;
    const float g = g_gate[bc];
    const size_t base = (size_t)bc * SPAT4;
    const int idx = blockIdx.x * 256 + threadIdx.x;    // 0..65535

    if (bc < KEEP_BC) {
        #pragma unroll
        for (int k = 0; k < 2; ++k) {
            const size_t i = base + idx + (size_t)k * (256 * 256);
            float4 v = x[i];                           // expected L2 hit
            v.x *= g; v.y *= g; v.z *= g; v.w *= g;
            __stcs(&out[i], v);
        }
    } else {
        #pragma unroll
        for (int k = 0; k < 2; ++k) {
            const size_t i = base + idx + (size_t)k * (256 * 256);
            float4 v = __ldcs(&x[i]);                  // stream
            v.x *= g; v.y *= g; v.z *= g; v.w *= g;
            __stcs(&out[i], v);
        }
    }
}

// ---------------------------------------------------------------------------
extern "C" void kernel_launch(void* const* d_in, const int* in_sizes, int n_in,
                              void* d_out, int out_size) {
    const float* x  = (const float*)d_in[0];   // [4,64,32,128,128]
    const float* w1 = (const float*)d_in[1];   // [4,64]
    const float* b1 = (const float*)d_in[2];   // [4]
    const float* w2 = (const float*)d_in[3];   // [64,4]
    const float* b2 = (const float*)d_in[4];   // [64]
    float* out = (float*)d_out;

    cca_reduce_se_kernel<<<dim3(PARTS, NBC), 256>>>((const float4*)x, w1, b1, w2, b2);

    // Scale kernel with programmatic dependent launch (overlap launch latency).
    cudaLaunchConfig_t cfg = {};
    cfg.gridDim  = dim3(256, NBC);
    cfg.blockDim = dim3(256);
    cfg.dynamicSmemBytes = 0;
    cfg.stream = 0;                                    // same (captured) stream
    cudaLaunchAttribute attrs[1];
    attrs[0].id = cudaLaunchAttributeProgrammaticStreamSerialization;
    attrs[0].val.programmaticStreamSerializationAllowed = 1;
    cfg.attrs = attrs;
    cfg.numAttrs = 1;
    cudaLaunchKernelEx(&cfg, cca_scale_kernel, (const float4*)x, (float4*)out);
}

// round 17
// speedup vs baseline: 1.0135x; 1.0135x over previous
#include <cuda_runtime.h>
#include <math.h>

// Problem constants
#define BATCH   4
#define CHANS   64
#define NBC     256                 // BATCH * CHANS
#define SPATIAL 524288              // 32*128*128 elements per (b,c)
#define SPAT4   131072              // SPATIAL / 4 (float4)
#define PARTS   8                   // reduction blocks per (b,c)
#define REDR    4                   // C // R = 64/16
#define NRED    (NBC * PARTS)       // 2048 reduce blocks

// Deterministic scratch (no device allocation allowed).
// Layout [part][bc]: the last block's epilogue reads coalesced (thread t
// reads column t), keeping the serialized gate tail short.
__device__ float g_part_s [NRED];
__device__ float g_part_ss[NRED];
__device__ float g_gate   [NBC];
__device__ unsigned int g_done;     // zero-init; reset by the last block each call

// ---------------------------------------------------------------------------
// Kernel 1: per-(b,c) partial sum / sum-of-squares, SE MLP fused into the
// last-finishing block (threadfence-reduction pattern).
// grid = (PARTS, NBC) = 2048 blocks x 256 thr, 64 float4/thread, coalesced.
// Measured 86.4% DRAM (machine ceiling for pure-read streaming).
// PDL ordering (race-safe): non-last blocks fire the PDL trigger after
// publishing their partial; the LAST block fires it only AFTER g_gate is
// published, so the secondary's cudaGridDependencySynchronize() provably
// orders the gate writes.
// ---------------------------------------------------------------------------
__global__ __launch_bounds__(256) void cca_reduce_se_kernel(
    const float4* __restrict__ x,
    const float*  __restrict__ w1, const float* __restrict__ b1,
    const float*  __restrict__ w2, const float* __restrict__ b2)
{
    const int part = blockIdx.x;      // 0..PARTS-1
    const int bc   = blockIdx.y;      // 0..NBC-1
    const int tid  = threadIdx.x;

    const float4* p = x + (size_t)bc * SPAT4 + (size_t)part * (SPAT4 / PARTS);

    float s = 0.f, ss = 0.f;
    #pragma unroll 16
    for (int k = 0; k < 64; ++k) {
        float4 v = p[tid + k * 256];
        s  += v.x + v.y + v.z + v.w;
        ss += v.x * v.x + v.y * v.y + v.z * v.z + v.w * v.w;
    }

    // warp reduce
    #pragma unroll
    for (int o = 16; o > 0; o >>= 1) {
        s  += __shfl_xor_sync(0xffffffffu, s,  o);
        ss += __shfl_xor_sync(0xffffffffu, ss, o);
    }

    __shared__ float sh_s[8], sh_ss[8];
    __shared__ bool  sh_last;
    const int w = tid >> 5;
    if ((tid & 31) == 0) { sh_s[w] = s; sh_ss[w] = ss; }
    __syncthreads();

    if (tid == 0) {
        float ts = 0.f, tss = 0.f;
        #pragma unroll
        for (int i = 0; i < 8; ++i) { ts += sh_s[i]; tss += sh_ss[i]; }
        g_part_s [part * NBC + bc] = ts;               // [part][bc] layout
        g_part_ss[part * NBC + bc] = tss;
        __threadfence();                               // publish partials
        unsigned int prev = atomicAdd(&g_done, 1u);
        sh_last = (prev == NRED - 1u);
    }
    __syncthreads();
    if (!sh_last) {
        cudaTriggerProgrammaticLaunchCompletion();     // partials published
        return;
    }

    // ---- Last block: finish reduction + SE MLP (thread t = bc index) ----
    __threadfence();                                   // acquire partials
    const int t = tid;

    float fs = 0.f, fss = 0.f;
    #pragma unroll
    for (int i = 0; i < PARTS; ++i) {                  // coalesced column reads
        fs  += g_part_s [i * NBC + t];
        fss += g_part_ss[i * NBC + t];
    }
    const float invN = 1.0f / (float)SPATIAL;
    const float mean = fs * invN;
    const float var  = fmaxf(fss * invN - mean * mean, 0.f);
    const float stdv = sqrtf(var);

    __shared__ float y[NBC];
    y[t] = stdv + mean;
    __syncthreads();

    __shared__ float h[BATCH * REDR];
    if (t < BATCH * REDR) {
        const int b = t / REDR;
        const int r = t % REDR;
        float acc = b1[r];
        #pragma unroll
        for (int c = 0; c < CHANS; ++c)
            acc += w1[r * CHANS + c] * y[b * CHANS + c];
        h[t] = fmaxf(acc, 0.f);
    }
    __syncthreads();

    const int b = t / CHANS;
    const int c = t % CHANS;
    float acc = b2[c];
    #pragma unroll
    for (int r = 0; r < REDR; ++r)
        acc += w2[c * REDR + r] * h[b * REDR + r];
    g_gate[t] = 1.0f / (1.0f + expf(-acc));

    if (t == 0) g_done = 0;                            // reset for next replay
    __threadfence();                                   // publish gate + reset
    __syncthreads();                                   // all gate writes done
    cudaTriggerProgrammaticLaunchCompletion();         // NOW release secondary
}

// ---------------------------------------------------------------------------
// Kernel 2: out = x * g[bc]. PDL secondary, sync at top. Peak of the
// measured granularity ladder: grid (256, NBC) = 65536 blocks,
// 2 float4/thread (77.7%@1k, 82.7%@8k, 85.5%@32k, 86.3%@64k, 83.7%@128k).
// Plain loads/stores -- all cache-hint variants measured slower.
// ---------------------------------------------------------------------------
__global__ __launch_bounds__(256) void cca_scale_kernel(const float4* __restrict__ x,
                                                        float4* __restrict__ out) {
    cudaGridDependencySynchronize();                   // gate provably visible

    const int bc = blockIdx.y;
    const float g = g_gate[bc];
    const size_t base = (size_t)bc * SPAT4;
    const int idx = blockIdx.x * 256 + threadIdx.x;    // 0..65535

    #pragma unroll
    for (int k = 0; k < 2; ++k) {
        const size_t i = base + idx + (size_t)k * (256 * 256);
        float4 v = x[i];
        v.x *= g; v.y *= g; v.z *= g; v.w *= g;
        out[i] = v;
    }
}

// ---------------------------------------------------------------------------
extern "C" void kernel_launch(void* const* d_in, const int* in_sizes, int n_in,
                              void* d_out, int out_size) {
    const float* x  = (const float*)d_in[0];   // [4,64,32,128,128]
    const float* w1 = (const float*)d_in[1];   // [4,64]
    const float* b1 = (const float*)d_in[2];   // [4]
    const float* w2 = (const float*)d_in[3];   // [64,4]
    const float* b2 = (const float*)d_in[4];   // [64]
    float* out = (float*)d_out;

    cca_reduce_se_kernel<<<dim3(PARTS, NBC), 256>>>((const float4*)x, w1, b1, w2, b2);

    // Scale kernel with programmatic dependent launch (overlap launch latency).
    cudaLaunchConfig_t cfg = {};
    cfg.gridDim  = dim3(256, NBC);
    cfg.blockDim = dim3(256);
    cfg.dynamicSmemBytes = 0;
    cfg.stream = 0;                                    // same (captured) stream
    cudaLaunchAttribute attrs[1];
    attrs[0].id = cudaLaunchAttributeProgrammaticStreamSerialization;
    attrs[0].val.programmaticStreamSerializationAllowed = 1;
    cfg.attrs = attrs;
    cfg.numAttrs = 1;
    cudaLaunchKernelEx(&cfg, cca_scale_kernel, (const float4*)x, (float4*)out);
}